// round 13
// baseline (speedup 1.0000x reference)
#include <cuda_runtime.h>
#include <cuda_fp16.h>
#include <math.h>
#include <stdint.h>

// ---------------- problem constants ----------------
#define BATCH 64
#define HS_   56
#define CC    128
#define NH_   4
#define HID_  512
#define PIX   (BATCH*HS_*HS_)      // 200704
#define M1_   PIX                  // window-token rows
#define M2_   (BATCH*28*28)        // 50176 merged rows

// weight scratch offsets (halves)
#define WOFF_QKV   0
#define WOFF_PROJ  49152
#define WOFF_FC1   65536
#define WOFF_FC2   131072
#define WOFF_MRG   196608
#define WTOT       327680

// ---------------- scratch (static device memory; allocation-free) ----------
__device__ __half g_hw[(size_t)M1_*CC];      // LN output (fp16)
__device__ __half g_qkv[(size_t)M1_*3*CC];   // qkv projections (fp16)
__device__ __half g_o[(size_t)M1_*CC];       // attn out / merged xm (fp16)
__device__ float  g_xres[(size_t)M1_*CC];    // residual stream (fp32, pixel layout)
__device__ __half g_fc1[(size_t)M1_*HID_];   // fc1+gelu output (fp16)
__device__ __half g_wt[WTOT];                // fp16 weights
__device__ float  g_bias[64*4*2401];         // combined rpb+mask per (wimg, head)

// ---------------- helpers ----------------
__device__ __forceinline__ uint32_t f2tf32(float x) {
    uint32_t r; asm("cvt.rna.tf32.f32 %0, %1;" : "=r"(r) : "f"(x)); return r;
}
__device__ __forceinline__ float tf32r(float x) { return __uint_as_float(f2tf32(x)); }
__device__ __forceinline__ void mma_tf32(float* c, const uint32_t* a, uint32_t b0, uint32_t b1) {
    asm volatile("mma.sync.aligned.m16n8k8.row.col.f32.tf32.tf32.f32 "
        "{%0,%1,%2,%3}, {%4,%5,%6,%7}, {%8,%9}, {%0,%1,%2,%3};\n"
        : "+f"(c[0]), "+f"(c[1]), "+f"(c[2]), "+f"(c[3])
        : "r"(a[0]), "r"(a[1]), "r"(a[2]), "r"(a[3]), "r"(b0), "r"(b1));
}
__device__ __forceinline__ void mma_f16(float* c, const uint32_t* a, uint32_t b0, uint32_t b1) {
    asm volatile("mma.sync.aligned.m16n8k16.row.col.f32.f16.f16.f32 "
        "{%0,%1,%2,%3}, {%4,%5,%6,%7}, {%8,%9}, {%0,%1,%2,%3};\n"
        : "+f"(c[0]), "+f"(c[1]), "+f"(c[2]), "+f"(c[3])
        : "r"(a[0]), "r"(a[1]), "r"(a[2]), "r"(a[3]), "r"(b0), "r"(b1));
}
__device__ __forceinline__ void ldsm_x4(uint32_t* r, uint32_t saddr) {
    asm volatile("ldmatrix.sync.aligned.m8n8.x4.shared.b16 {%0,%1,%2,%3}, [%4];"
        : "=r"(r[0]), "=r"(r[1]), "=r"(r[2]), "=r"(r[3]) : "r"(saddr));
}
__device__ __forceinline__ void cp_async16(uint32_t saddr, const void* gptr) {
    asm volatile("cp.async.cg.shared.global [%0], [%1], 16;\n" :: "r"(saddr), "l"(gptr));
}
__device__ __forceinline__ void cp_commit() { asm volatile("cp.async.commit_group;\n"); }
__device__ __forceinline__ void cp_wait1() { asm volatile("cp.async.wait_group 1;\n"); }
__device__ __forceinline__ void cp_wait0() { asm volatile("cp.async.wait_group 0;\n"); }

// ---------------- weight pre-convert to fp16 ----------------
__global__ void round_w_kernel(const float* __restrict__ qkv_w, const float* __restrict__ proj_w,
                               const float* __restrict__ fc1_w, const float* __restrict__ fc2_w,
                               const float* __restrict__ merge_w)
{
    int i = blockIdx.x * blockDim.x + threadIdx.x;
    float v;
    if      (i < WOFF_PROJ) v = qkv_w[i];
    else if (i < WOFF_FC1)  v = proj_w[i - WOFF_PROJ];
    else if (i < WOFF_FC2)  v = fc1_w[i - WOFF_FC1];
    else if (i < WOFF_MRG)  v = fc2_w[i - WOFF_FC2];
    else                    v = merge_w[i - WOFF_MRG];
    g_wt[i] = __float2half(v);
}

// ---------------- combined attention bias table: rpb[rel]+mask ------------
__global__ void bias_prep_kernel(const float* __restrict__ rpb,
                                 const int* __restrict__ rel,
                                 const float* __restrict__ mask)
{
    int wimg = blockIdx.x, h = blockIdx.y;
    float* dst = g_bias + ((size_t)wimg*4 + h)*2401;
    const float* msk = mask + (size_t)wimg*2401;
    for (int i = threadIdx.x; i < 2401; i += blockDim.x)
        dst[i] = rpb[rel[i]*4 + h] + msk[i];
}

// ---------------- helper: store 4 floats as 4 halves (8B) ----------------
__device__ __forceinline__ void st_half4(__half* p, float a, float b, float c, float d) {
    __half2 h0 = __floats2half2_rn(a, b);
    __half2 h1 = __floats2half2_rn(c, d);
    uint2 u;
    u.x = *(uint32_t*)&h0;
    u.y = *(uint32_t*)&h1;
    *(uint2*)p = u;
}

// ---------------- LN1 + roll(-3,-3) + window partition (fp16 out) --------
__global__ void ln1_win_kernel(const float* __restrict__ x,
                               const float* __restrict__ gw,
                               const float* __restrict__ gb)
{
    int warp = (blockIdx.x * blockDim.x + threadIdx.x) >> 5;
    int lane = threadIdx.x & 31;
    int b   = warp / 3136;
    int rem = warp - b * 3136;
    int i = rem / 56;
    int j = rem - i * 56;
    int si = i + 3; if (si >= 56) si -= 56;
    int sj = j + 3; if (sj >= 56) sj -= 56;
    float4 v = *(const float4*)(x + ((((size_t)b*56 + si)*56) + sj)*128 + lane*4);
    float s  = v.x + v.y + v.z + v.w;
    float ss = v.x*v.x + v.y*v.y + v.z*v.z + v.w*v.w;
    #pragma unroll
    for (int o = 16; o; o >>= 1) {
        s  += __shfl_xor_sync(0xffffffffu, s,  o);
        ss += __shfl_xor_sync(0xffffffffu, ss, o);
    }
    float mean = s * (1.0f/128.0f);
    float var  = ss * (1.0f/128.0f) - mean*mean;
    float rstd = rsqrtf(var + 1e-5f);
    float4 wv = *(const float4*)(gw + lane*4);
    float4 bv = *(const float4*)(gb + lane*4);
    int i7 = i / 7, j7 = j / 7;
    int widx = i7*8 + j7;
    int n    = (i - i7*7)*7 + (j - j7*7);
    size_t row = (size_t)(b*64 + widx)*49 + n;
    st_half4(g_hw + row*128 + lane*4,
             (v.x - mean)*rstd*wv.x + bv.x,
             (v.y - mean)*rstd*wv.y + bv.y,
             (v.z - mean)*rstd*wv.z + bv.z,
             (v.w - mean)*rstd*wv.w + bv.w);
}

// ---------------- LN2 (pixel layout): g_xres -> g_hw (fp16) ---------------
__global__ void ln2_kernel(const float* __restrict__ gw, const float* __restrict__ gb)
{
    int warp = (blockIdx.x * blockDim.x + threadIdx.x) >> 5;
    int lane = threadIdx.x & 31;
    float4 v = *(const float4*)(g_xres + (size_t)warp*128 + lane*4);
    float s  = v.x + v.y + v.z + v.w;
    float ss = v.x*v.x + v.y*v.y + v.z*v.z + v.w*v.w;
    #pragma unroll
    for (int o = 16; o; o >>= 1) {
        s  += __shfl_xor_sync(0xffffffffu, s,  o);
        ss += __shfl_xor_sync(0xffffffffu, ss, o);
    }
    float mean = s * (1.0f/128.0f);
    float var  = ss * (1.0f/128.0f) - mean*mean;
    float rstd = rsqrtf(var + 1e-5f);
    float4 wv = *(const float4*)(gw + lane*4);
    float4 bv = *(const float4*)(gb + lane*4);
    st_half4(g_hw + (size_t)warp*128 + lane*4,
             (v.x - mean)*rstd*wv.x + bv.x,
             (v.y - mean)*rstd*wv.y + bv.y,
             (v.z - mean)*rstd*wv.z + bv.z,
             (v.w - mean)*rstd*wv.w + bv.w);
}

// ---------------- patch-merge gather + LN(512): g_xres -> g_o (fp16) ------
__global__ void merge_ln_kernel(const float* __restrict__ gw, const float* __restrict__ gb)
{
    int warp = (blockIdx.x * blockDim.x + threadIdx.x) >> 5;
    int lane = threadIdx.x & 31;
    int b   = warp / 784;
    int rem = warp - b * 784;
    int i2 = rem / 28;
    int j2 = rem - i2 * 28;
    int i0 = 2*i2, j0 = 2*j2;
    const float* p0 = g_xres + (((size_t)b*56 + i0    )*56 + j0    )*128;
    const float* p1 = g_xres + (((size_t)b*56 + i0 + 1)*56 + j0    )*128;
    const float* p2 = g_xres + (((size_t)b*56 + i0    )*56 + j0 + 1)*128;
    const float* p3 = g_xres + (((size_t)b*56 + i0 + 1)*56 + j0 + 1)*128;
    float4 v[4];
    v[0] = *(const float4*)(p0 + lane*4);
    v[1] = *(const float4*)(p1 + lane*4);
    v[2] = *(const float4*)(p2 + lane*4);
    v[3] = *(const float4*)(p3 + lane*4);
    float s = 0.f, ss = 0.f;
    #pragma unroll
    for (int q = 0; q < 4; q++) {
        s  += v[q].x + v[q].y + v[q].z + v[q].w;
        ss += v[q].x*v[q].x + v[q].y*v[q].y + v[q].z*v[q].z + v[q].w*v[q].w;
    }
    #pragma unroll
    for (int o = 16; o; o >>= 1) {
        s  += __shfl_xor_sync(0xffffffffu, s,  o);
        ss += __shfl_xor_sync(0xffffffffu, ss, o);
    }
    float mean = s * (1.0f/512.0f);
    float var  = ss * (1.0f/512.0f) - mean*mean;
    float rstd = rsqrtf(var + 1e-5f);
    __half* out = g_o + (size_t)warp*512;
    #pragma unroll
    for (int q = 0; q < 4; q++) {
        int c = q*128 + lane*4;
        float4 wv = *(const float4*)(gw + c);
        float4 bv = *(const float4*)(gb + c);
        st_half4(out + c,
                 (v[q].x - mean)*rstd*wv.x + bv.x,
                 (v[q].y - mean)*rstd*wv.y + bv.y,
                 (v[q].z - mean)*rstd*wv.z + bv.z,
                 (v[q].w - mean)*rstd*wv.w + bv.w);
    }
}

// ---------------- MMA attention: block = one window, warp = one head ------
// fp16 I/O, tf32 internals (unchanged, proven correct).
#define AQ_STR 132
#define AK_STR 132
#define AV_STR 136
#define AP_STR 60
#define AOFF_K (64*AQ_STR)                  // 8448
#define AOFF_V (AOFF_K + 56*AK_STR)         // 15840
#define AOFF_P (AOFF_V + 56*AV_STR)         // 23456
#define AOFF_I (AOFF_P + 4*16*AP_STR)       // 27296
#define ATT_SMEM ((AOFF_I + 4*16)*4)        // 109440 bytes

__global__ __launch_bounds__(128) void attn_kernel(
    const __half* __restrict__ qkv, __half* __restrict__ outp)
{
    extern __shared__ float sm[];
    float* qs = sm;
    float* ks = sm + AOFF_K;
    float* vs = sm + AOFF_V;
    const int t    = threadIdx.x;
    const int warp = t >> 5;
    const int lane = t & 31;
    const int win  = blockIdx.x;
    float* Pt   = sm + AOFF_P + warp*16*AP_STR;
    float* invs = sm + AOFF_I + warp*16;

    const __half* base = qkv + (size_t)win*49*384;
    for (int idx = t; idx < 49*48; idx += 128) {
        int row = idx / 48;
        int sub = idx - row*48;
        int kind = sub >> 4;
        int c8 = sub & 15;
        uint4 hv = *(const uint4*)(base + (size_t)row*384 + kind*128 + c8*8);
        const __half2* hp = (const __half2*)&hv;
        float* dst = (kind == 0 ? qs + row*AQ_STR :
                      kind == 1 ? ks + row*AK_STR : vs + row*AV_STR) + c8*8;
        float2 f0 = __half22float2(hp[0]);
        float2 f1 = __half22float2(hp[1]);
        float2 f2 = __half22float2(hp[2]);
        float2 f3 = __half22float2(hp[3]);
        float4 o0; o0.x = f0.x; o0.y = f0.y; o0.z = f1.x; o0.w = f1.y;
        float4 o1; o1.x = f2.x; o1.y = f2.y; o1.z = f3.x; o1.w = f3.y;
        *(float4*)dst = o0;
        *(float4*)(dst + 4) = o1;
    }
    for (int idx = t; idx < 7*AV_STR; idx += 128) {
        int r = idx / AV_STR, c = idx - r*AV_STR;
        vs[(49+r)*AV_STR + c] = 0.f;
        if (c < AK_STR) ks[(49+r)*AK_STR + c] = 0.f;
    }
    __syncthreads();

    const int h   = warp;
    const int qr  = lane >> 2;
    const int qc  = lane & 3;
    const int h32 = h * 32;
    const float* comb = g_bias + (size_t)((win & 63)*4 + h)*2401;
    __half* obase = outp + (size_t)win*49*128 + h32;

    for (int mt = 0; mt < 4; mt++) {
        const int r0 = mt*16 + qr;
        const int r1 = r0 + 8;
        float s[7][4];
        #pragma unroll
        for (int jn = 0; jn < 7; jn++)
            #pragma unroll
            for (int c = 0; c < 4; c++) s[jn][c] = 0.f;
        #pragma unroll
        for (int kb = 0; kb < 32; kb += 8) {
            uint32_t a[4];
            a[0] = __float_as_uint(qs[(size_t)r0*AQ_STR + h32 + kb + qc    ]);
            a[1] = __float_as_uint(qs[(size_t)r1*AQ_STR + h32 + kb + qc    ]);
            a[2] = __float_as_uint(qs[(size_t)r0*AQ_STR + h32 + kb + qc + 4]);
            a[3] = __float_as_uint(qs[(size_t)r1*AQ_STR + h32 + kb + qc + 4]);
            #pragma unroll
            for (int jn = 0; jn < 7; jn++) {
                int n0 = jn*8 + qr;
                uint32_t b0 = __float_as_uint(ks[(size_t)n0*AK_STR + h32 + kb + qc    ]);
                uint32_t b1 = __float_as_uint(ks[(size_t)n0*AK_STR + h32 + kb + qc + 4]);
                mma_tf32(s[jn], a, b0, b1);
            }
        }
        const bool v0 = (r0 < 49), v1 = (r1 < 49);
        float mx0 = -1e30f, mx1 = -1e30f;
        #pragma unroll
        for (int jn = 0; jn < 7; jn++) {
            #pragma unroll
            for (int e = 0; e < 2; e++) {
                int col = jn*8 + qc*2 + e;
                if (col < 49) {
                    if (v0) s[jn][e]     += comb[r0*49 + col];
                    if (v1) s[jn][2 + e] += comb[r1*49 + col];
                } else {
                    s[jn][e] = -1e30f; s[jn][2 + e] = -1e30f;
                }
                mx0 = fmaxf(mx0, s[jn][e]);
                mx1 = fmaxf(mx1, s[jn][2 + e]);
            }
        }
        #pragma unroll
        for (int o = 1; o <= 2; o <<= 1) {
            mx0 = fmaxf(mx0, __shfl_xor_sync(0xffffffffu, mx0, o));
            mx1 = fmaxf(mx1, __shfl_xor_sync(0xffffffffu, mx1, o));
        }
        float sum0 = 0.f, sum1 = 0.f;
        #pragma unroll
        for (int jn = 0; jn < 7; jn++) {
            #pragma unroll
            for (int e = 0; e < 2; e++) {
                int col = jn*8 + qc*2 + e;
                float e0 = __expf(s[jn][e]     - mx0);
                float e1 = __expf(s[jn][2 + e] - mx1);
                sum0 += e0; sum1 += e1;
                Pt[qr*AP_STR       + col] = tf32r(e0);
                Pt[(qr + 8)*AP_STR + col] = tf32r(e1);
            }
        }
        #pragma unroll
        for (int o = 1; o <= 2; o <<= 1) {
            sum0 += __shfl_xor_sync(0xffffffffu, sum0, o);
            sum1 += __shfl_xor_sync(0xffffffffu, sum1, o);
        }
        if (qc == 0) {
            invs[qr]     = 1.0f / sum0;
            invs[qr + 8] = 1.0f / sum1;
        }
        __syncwarp();
        float o[4][4];
        #pragma unroll
        for (int jn = 0; jn < 4; jn++)
            #pragma unroll
            for (int c = 0; c < 4; c++) o[jn][c] = 0.f;
        #pragma unroll
        for (int ks2 = 0; ks2 < 7; ks2++) {
            const int kb = ks2*8;
            uint32_t a[4];
            a[0] = __float_as_uint(Pt[qr*AP_STR       + kb + qc    ]);
            a[1] = __float_as_uint(Pt[(qr + 8)*AP_STR + kb + qc    ]);
            a[2] = __float_as_uint(Pt[qr*AP_STR       + kb + qc + 4]);
            a[3] = __float_as_uint(Pt[(qr + 8)*AP_STR + kb + qc + 4]);
            #pragma unroll
            for (int jn = 0; jn < 4; jn++) {
                int n0 = jn*8 + qr;
                uint32_t b0 = __float_as_uint(vs[(size_t)(kb + qc    )*AV_STR + h32 + n0]);
                uint32_t b1 = __float_as_uint(vs[(size_t)(kb + qc + 4)*AV_STR + h32 + n0]);
                mma_tf32(o[jn], a, b0, b1);
            }
        }
        float i0 = invs[qr], i1 = invs[qr + 8];
        #pragma unroll
        for (int jn = 0; jn < 4; jn++) {
            int col = jn*8 + qc*2;
            if (v0) {
                __half2 f = __floats2half2_rn(o[jn][0]*i0, o[jn][1]*i0);
                *(__half2*)(obase + (size_t)r0*128 + col) = f;
            }
            if (v1) {
                __half2 f = __floats2half2_rn(o[jn][2]*i1, o[jn][3]*i1);
                *(__half2*)(obase + (size_t)r1*128 + col) = f;
            }
        }
        __syncwarp();
    }
}

// ---------------- FP16 tensor-core GEMM, 3-stage ring, 1 sync/iter -------
// C[M,Nd] = A[M,K] @ W[Nd,K]^T + epilogue. A and W are fp16.
// Block tile 128x128, BK=32, 8 warps (4m x 2n), warp tile 32x64, m16n8k16.
// Loop order: wait -> sync -> prefetch(slot+2) -> mma(slot). The top barrier
// guarantees all warps finished reading slot-1 (== slot+2 mod 3) at it-1, so
// the prefetch is WAR-safe with a single barrier per iteration.
// Fragments via ldmatrix.m8n8.x4.b16 (12 LDSM vs 48 LDS per BK-iter).
#define TG_STG_BYTES (256*80)       // one stage: (128 A + 128 B rows) * 80B
#define TG_NSTG 3
#define TG_SMEM (TG_STG_BYTES*TG_NSTG)   // 61440 bytes

template<int EPI>
__global__ __launch_bounds__(256, 2) void tgemm_kernel(
    const __half* __restrict__ A, const __half* __restrict__ W,
    const float* __restrict__ bias, void* __restrict__ Cv,
    const float* __restrict__ aux, int M, int Nd, int K)
{
    extern __shared__ __align__(16) char dsm[];
    const int t    = threadIdx.x;
    const int warp = t >> 5;
    const int lane = t & 31;
    const int qr   = lane >> 2;
    const int qc   = lane & 3;
    const int wm   = warp & 3;    // m warp 0..3
    const int wn   = warp >> 2;   // n warp 0..1
    const int bm   = blockIdx.y * 128;
    const int bn   = blockIdx.x * 128;
    const int rowX = t >> 2;      // 0..63
    const int cX   = t & 3;       // 8-half chunk within 32-half row slice

    const __half* aG = A + (size_t)(bm + rowX)*K + cX*8;
    const __half* wG = W + (size_t)(bn + rowX)*K + cX*8;
    const size_t r64 = (size_t)64 * K;

    uint32_t s0 = (uint32_t)__cvta_generic_to_shared(dsm);
    const uint32_t sA = s0 + rowX*80 + cX*16;
    const uint32_t sB = sA + 128*80;

    // ldmatrix per-lane address offset: row (lane&15), half-col (lane>>4)*8
    const uint32_t laneOff = (uint32_t)(lane & 15)*80 + (uint32_t)(lane >> 4)*16;

    float acc[2][8][4] = {};
    const int iters = K >> 5;   // >= 4 always (K = 128 or 512)

    #define TG_STAGE_LOAD(st, kk) do {                        \
        uint32_t off_ = (uint32_t)(st)*TG_STG_BYTES;          \
        const __half* ag_ = aG + (size_t)(kk)*32;             \
        const __half* wg_ = wG + (size_t)(kk)*32;             \
        cp_async16(sA + off_,         ag_);                   \
        cp_async16(sA + off_ + 64*80, ag_ + r64);             \
        cp_async16(sB + off_,         wg_);                   \
        cp_async16(sB + off_ + 64*80, wg_ + r64);             \
        cp_commit();                                          \
    } while (0)

    // prologue: stages 0 and 1
    TG_STAGE_LOAD(0, 0);
    TG_STAGE_LOAD(1, 1);

    int slot = 0;
    for (int it = 0; it < iters; it++) {
        if (it + 1 < iters) cp_wait1(); else cp_wait0();
        __syncthreads();
        if (it + 2 < iters) {
            int ps = slot + 2; if (ps >= TG_NSTG) ps -= TG_NSTG;
            TG_STAGE_LOAD(ps, it + 2);
        }

        const uint32_t stg   = s0 + (uint32_t)slot*TG_STG_BYTES;
        const uint32_t aBase = stg + (uint32_t)(wm*32)*80;
        const uint32_t bBase = stg + 128*80 + (uint32_t)(wn*64)*80;
        #pragma unroll
        for (int ks = 0; ks < 2; ks++) {
            const uint32_t kof = (uint32_t)ks*32;   // 16 halves = 32 bytes
            uint32_t af[2][4];
            ldsm_x4(af[0], aBase + kof + laneOff);
            ldsm_x4(af[1], aBase + 16*80 + kof + laneOff);
            #pragma unroll
            for (int p = 0; p < 4; p++) {
                uint32_t bf[4];   // {b0(j=2p), b0(j=2p+1), b1(2p), b1(2p+1)}
                ldsm_x4(bf, bBase + (uint32_t)(p*16)*80 + kof + laneOff);
                mma_f16(acc[0][2*p    ], af[0], bf[0], bf[2]);
                mma_f16(acc[1][2*p    ], af[1], bf[0], bf[2]);
                mma_f16(acc[0][2*p + 1], af[0], bf[1], bf[3]);
                mma_f16(acc[1][2*p + 1], af[1], bf[1], bf[3]);
            }
        }
        if (++slot == TG_NSTG) slot = 0;
    }
    #undef TG_STAGE_LOAD

    // ---- epilogue (vectorized pair stores) ----
    float*  Cf = (float*)Cv;
    __half* Ch = (__half*)Cv;
    #pragma unroll
    for (int i = 0; i < 2; i++) {
        #pragma unroll
        for (int half_ = 0; half_ < 2; half_++) {
            const int m = bm + wm*32 + i*16 + qr + half_*8;
            size_t obase;
            if (EPI == 2) {
                int win = m / 49, nn = m - win*49;
                int bb = win >> 6, w = win & 63;
                int n7 = nn / 7;
                int pi = (w >> 3)*7 + n7;
                int pj = (w & 7)*7 + (nn - n7*7);
                int ii = pi + 3; if (ii >= 56) ii -= 56;
                int jj = pj + 3; if (jj >= 56) jj -= 56;
                obase = (((size_t)bb*56 + ii)*56 + jj)*128;
            } else {
                obase = (size_t)m * Nd;
            }
            #pragma unroll
            for (int j = 0; j < 8; j++) {
                const int n = bn + wn*64 + j*8 + qc*2;
                float v0 = acc[i][j][half_*2];
                float v1 = acc[i][j][half_*2 + 1];
                if (EPI == 0) {
                    float2 f; f.x = v0; f.y = v1;
                    *(float2*)(Cf + obase + n) = f;
                } else if (EPI == 1) {
                    v0 += bias[n]; v1 += bias[n + 1];
                    if (n < 128) { v0 *= 0.17677669529663687f; v1 *= 0.17677669529663687f; }
                    *(__half2*)(Ch + obase + n) = __floats2half2_rn(v0, v1);
                } else if (EPI == 2) {
                    v0 += bias[n]; v1 += bias[n + 1];
                    float2 a2 = *(const float2*)(aux + obase + n);
                    float2 f; f.x = v0 + a2.x; f.y = v1 + a2.y;
                    *(float2*)(Cf + obase + n) = f;
                } else if (EPI == 3) {
                    v0 += bias[n]; v1 += bias[n + 1];
                    v0 = 0.5f * v0 * (1.0f + erff(v0 * 0.70710678118654752f));
                    v1 = 0.5f * v1 * (1.0f + erff(v1 * 0.70710678118654752f));
                    *(__half2*)(Ch + obase + n) = __floats2half2_rn(v0, v1);
                } else { // EPI == 4
                    v0 += bias[n]; v1 += bias[n + 1];
                    float2 a2 = *(const float2*)(aux + obase + n);
                    float2 f; f.x = v0 + a2.x; f.y = v1 + a2.y;
                    *(float2*)(Cf + obase + n) = f;
                }
            }
        }
    }
}

// ---------------- launcher ----------------
extern "C" void kernel_launch(void* const* d_in, const int* in_sizes, int n_in,
                              void* d_out, int out_size)
{
    const float* x       = (const float*)d_in[0];
    const float* n1w     = (const float*)d_in[1];
    const float* n1b     = (const float*)d_in[2];
    const float* qkv_w   = (const float*)d_in[3];
    const float* qkv_b   = (const float*)d_in[4];
    const float* proj_w  = (const float*)d_in[5];
    const float* proj_b  = (const float*)d_in[6];
    const float* rpb     = (const float*)d_in[7];
    const float* n2w     = (const float*)d_in[8];
    const float* n2b     = (const float*)d_in[9];
    const float* fc1_w   = (const float*)d_in[10];
    const float* fc1_b   = (const float*)d_in[11];
    const float* fc2_w   = (const float*)d_in[12];
    const float* fc2_b   = (const float*)d_in[13];
    const float* mnw     = (const float*)d_in[14];
    const float* mnb     = (const float*)d_in[15];
    const float* merge_w = (const float*)d_in[16];
    const int*   rel_idx = (const int*)d_in[17];
    const float* amask   = (const float*)d_in[18];
    float* out = (float*)d_out;

    __half *hw, *qkv, *o, *fc1, *wt;
    float *xres;
    cudaGetSymbolAddress((void**)&hw,   g_hw);
    cudaGetSymbolAddress((void**)&qkv,  g_qkv);
    cudaGetSymbolAddress((void**)&o,    g_o);
    cudaGetSymbolAddress((void**)&xres, g_xres);
    cudaGetSymbolAddress((void**)&fc1,  g_fc1);
    cudaGetSymbolAddress((void**)&wt,   g_wt);

    cudaFuncSetAttribute(tgemm_kernel<0>, cudaFuncAttributeMaxDynamicSharedMemorySize, TG_SMEM);
    cudaFuncSetAttribute(tgemm_kernel<1>, cudaFuncAttributeMaxDynamicSharedMemorySize, TG_SMEM);
    cudaFuncSetAttribute(tgemm_kernel<2>, cudaFuncAttributeMaxDynamicSharedMemorySize, TG_SMEM);
    cudaFuncSetAttribute(tgemm_kernel<3>, cudaFuncAttributeMaxDynamicSharedMemorySize, TG_SMEM);
    cudaFuncSetAttribute(tgemm_kernel<4>, cudaFuncAttributeMaxDynamicSharedMemorySize, TG_SMEM);
    cudaFuncSetAttribute(attn_kernel, cudaFuncAttributeMaxDynamicSharedMemorySize, ATT_SMEM);

    // 0. pre-convert weights to fp16; build combined attention bias table
    round_w_kernel<<<WTOT/256, 256>>>(qkv_w, proj_w, fc1_w, fc2_w, merge_w);
    bias_prep_kernel<<<dim3(64, 4), 256>>>(rpb, rel_idx, amask);
    // 1. LN1 + roll + window partition (fp16 out)
    ln1_win_kernel<<<PIX/8, 256>>>(x, n1w, n1b);
    // 2. qkv GEMM (scale folded into q; fp16 out)
    tgemm_kernel<1><<<dim3(3, M1_/128), 256, TG_SMEM>>>(hw, wt + WOFF_QKV, qkv_b, qkv, nullptr, M1_, 384, 128);
    // 3. windowed attention (tensor cores; fp16 out)
    attn_kernel<<<4096, 128, ATT_SMEM>>>(qkv, o);
    // 4. proj GEMM + window-reverse + roll-back + residual -> xres (fp32, pixel layout)
    tgemm_kernel<2><<<dim3(1, M1_/128), 256, TG_SMEM>>>(o, wt + WOFF_PROJ, proj_b, xres, x, M1_, 128, 128);
    // 5. LN2: xres -> g_hw (fp16)
    ln2_kernel<<<PIX/8, 256>>>(n2w, n2b);
    // 6. fc1 GEMM + GELU (fp16 out)
    tgemm_kernel<3><<<dim3(4, M1_/128), 256, TG_SMEM>>>(hw, wt + WOFF_FC1, fc1_b, fc1, nullptr, M1_, 512, 128);
    // 7. fc2 GEMM + residual (fp32, in place on xres)
    tgemm_kernel<4><<<dim3(1, M1_/128), 256, TG_SMEM>>>(fc1, wt + WOFF_FC2, fc2_b, xres, xres, M1_, 128, 512);
    // 8. patch-merge gather + LN(512): xres -> g_o (fp16, reuse as xm)
    merge_ln_kernel<<<M2_/8, 256>>>(mnw, mnb);
    // 9. merge GEMM -> output (fp32)
    tgemm_kernel<0><<<dim3(2, M2_/128), 256, TG_SMEM>>>(o, wt + WOFF_MRG, nullptr, out, nullptr, M2_, 256, 512);
}

// round 14
// speedup vs baseline: 1.0060x; 1.0060x over previous
#include <cuda_runtime.h>
#include <cuda_fp16.h>
#include <math.h>
#include <stdint.h>

// ---------------- problem constants ----------------
#define BATCH 64
#define HS_   56
#define CC    128
#define NH_   4
#define HID_  512
#define PIX   (BATCH*HS_*HS_)      // 200704
#define M1_   PIX                  // window-token rows
#define M2_   (BATCH*28*28)        // 50176 merged rows

// weight scratch offsets (halves)
#define WOFF_QKV   0
#define WOFF_PROJ  49152
#define WOFF_FC1   65536
#define WOFF_FC2   131072
#define WOFF_MRG   196608
#define WTOT       327680

// ---------------- scratch (static device memory; allocation-free) ----------
__device__ __half g_hw[(size_t)M1_*CC];      // LN output (fp16)
__device__ __half g_qkv[(size_t)M1_*3*CC];   // qkv projections (fp16)
__device__ __half g_o[(size_t)M1_*CC];       // attn out / merged xm (fp16)
__device__ float  g_xres[(size_t)M1_*CC];    // residual stream (fp32, pixel layout)
__device__ __half g_fc1[(size_t)M1_*HID_];   // fc1+gelu output (fp16)
__device__ __half g_wt[WTOT];                // fp16 weights
__device__ float  g_bias[64*4*2401];         // combined rpb+mask per (wimg, head)

// ---------------- helpers ----------------
__device__ __forceinline__ uint32_t f2tf32(float x) {
    uint32_t r; asm("cvt.rna.tf32.f32 %0, %1;" : "=r"(r) : "f"(x)); return r;
}
__device__ __forceinline__ float tf32r(float x) { return __uint_as_float(f2tf32(x)); }
__device__ __forceinline__ void mma_tf32(float* c, const uint32_t* a, uint32_t b0, uint32_t b1) {
    asm volatile("mma.sync.aligned.m16n8k8.row.col.f32.tf32.tf32.f32 "
        "{%0,%1,%2,%3}, {%4,%5,%6,%7}, {%8,%9}, {%0,%1,%2,%3};\n"
        : "+f"(c[0]), "+f"(c[1]), "+f"(c[2]), "+f"(c[3])
        : "r"(a[0]), "r"(a[1]), "r"(a[2]), "r"(a[3]), "r"(b0), "r"(b1));
}
__device__ __forceinline__ void mma_f16(float* c, const uint32_t* a, uint32_t b0, uint32_t b1) {
    asm volatile("mma.sync.aligned.m16n8k16.row.col.f32.f16.f16.f32 "
        "{%0,%1,%2,%3}, {%4,%5,%6,%7}, {%8,%9}, {%0,%1,%2,%3};\n"
        : "+f"(c[0]), "+f"(c[1]), "+f"(c[2]), "+f"(c[3])
        : "r"(a[0]), "r"(a[1]), "r"(a[2]), "r"(a[3]), "r"(b0), "r"(b1));
}
__device__ __forceinline__ void ldsm_x4(uint32_t* r, uint32_t saddr) {
    asm volatile("ldmatrix.sync.aligned.m8n8.x4.shared.b16 {%0,%1,%2,%3}, [%4];"
        : "=r"(r[0]), "=r"(r[1]), "=r"(r[2]), "=r"(r[3]) : "r"(saddr));
}
__device__ __forceinline__ void cp_async16(uint32_t saddr, const void* gptr) {
    asm volatile("cp.async.cg.shared.global [%0], [%1], 16;\n" :: "r"(saddr), "l"(gptr));
}
__device__ __forceinline__ void cp_commit() { asm volatile("cp.async.commit_group;\n"); }
__device__ __forceinline__ void cp_wait1() { asm volatile("cp.async.wait_group 1;\n"); }
__device__ __forceinline__ void cp_wait0() { asm volatile("cp.async.wait_group 0;\n"); }

// ---------------- weight pre-convert to fp16 ----------------
__global__ void round_w_kernel(const float* __restrict__ qkv_w, const float* __restrict__ proj_w,
                               const float* __restrict__ fc1_w, const float* __restrict__ fc2_w,
                               const float* __restrict__ merge_w)
{
    int i = blockIdx.x * blockDim.x + threadIdx.x;
    float v;
    if      (i < WOFF_PROJ) v = qkv_w[i];
    else if (i < WOFF_FC1)  v = proj_w[i - WOFF_PROJ];
    else if (i < WOFF_FC2)  v = fc1_w[i - WOFF_FC1];
    else if (i < WOFF_MRG)  v = fc2_w[i - WOFF_FC2];
    else                    v = merge_w[i - WOFF_MRG];
    g_wt[i] = __float2half(v);
}

// ---------------- combined attention bias table: rpb[rel]+mask ------------
__global__ void bias_prep_kernel(const float* __restrict__ rpb,
                                 const int* __restrict__ rel,
                                 const float* __restrict__ mask)
{
    int wimg = blockIdx.x, h = blockIdx.y;
    float* dst = g_bias + ((size_t)wimg*4 + h)*2401;
    const float* msk = mask + (size_t)wimg*2401;
    for (int i = threadIdx.x; i < 2401; i += blockDim.x)
        dst[i] = rpb[rel[i]*4 + h] + msk[i];
}

// ---------------- helper: store 4 floats as 4 halves (8B) ----------------
__device__ __forceinline__ void st_half4(__half* p, float a, float b, float c, float d) {
    __half2 h0 = __floats2half2_rn(a, b);
    __half2 h1 = __floats2half2_rn(c, d);
    uint2 u;
    u.x = *(uint32_t*)&h0;
    u.y = *(uint32_t*)&h1;
    *(uint2*)p = u;
}

// ---------------- LN1 + roll(-3,-3) + window partition (fp16 out) --------
__global__ void ln1_win_kernel(const float* __restrict__ x,
                               const float* __restrict__ gw,
                               const float* __restrict__ gb)
{
    int warp = (blockIdx.x * blockDim.x + threadIdx.x) >> 5;
    int lane = threadIdx.x & 31;
    int b   = warp / 3136;
    int rem = warp - b * 3136;
    int i = rem / 56;
    int j = rem - i * 56;
    int si = i + 3; if (si >= 56) si -= 56;
    int sj = j + 3; if (sj >= 56) sj -= 56;
    float4 v = *(const float4*)(x + ((((size_t)b*56 + si)*56) + sj)*128 + lane*4);
    float s  = v.x + v.y + v.z + v.w;
    float ss = v.x*v.x + v.y*v.y + v.z*v.z + v.w*v.w;
    #pragma unroll
    for (int o = 16; o; o >>= 1) {
        s  += __shfl_xor_sync(0xffffffffu, s,  o);
        ss += __shfl_xor_sync(0xffffffffu, ss, o);
    }
    float mean = s * (1.0f/128.0f);
    float var  = ss * (1.0f/128.0f) - mean*mean;
    float rstd = rsqrtf(var + 1e-5f);
    float4 wv = *(const float4*)(gw + lane*4);
    float4 bv = *(const float4*)(gb + lane*4);
    int i7 = i / 7, j7 = j / 7;
    int widx = i7*8 + j7;
    int n    = (i - i7*7)*7 + (j - j7*7);
    size_t row = (size_t)(b*64 + widx)*49 + n;
    st_half4(g_hw + row*128 + lane*4,
             (v.x - mean)*rstd*wv.x + bv.x,
             (v.y - mean)*rstd*wv.y + bv.y,
             (v.z - mean)*rstd*wv.z + bv.z,
             (v.w - mean)*rstd*wv.w + bv.w);
}

// ---------------- LN2 (pixel layout): g_xres -> g_hw (fp16) ---------------
__global__ void ln2_kernel(const float* __restrict__ gw, const float* __restrict__ gb)
{
    int warp = (blockIdx.x * blockDim.x + threadIdx.x) >> 5;
    int lane = threadIdx.x & 31;
    float4 v = *(const float4*)(g_xres + (size_t)warp*128 + lane*4);
    float s  = v.x + v.y + v.z + v.w;
    float ss = v.x*v.x + v.y*v.y + v.z*v.z + v.w*v.w;
    #pragma unroll
    for (int o = 16; o; o >>= 1) {
        s  += __shfl_xor_sync(0xffffffffu, s,  o);
        ss += __shfl_xor_sync(0xffffffffu, ss, o);
    }
    float mean = s * (1.0f/128.0f);
    float var  = ss * (1.0f/128.0f) - mean*mean;
    float rstd = rsqrtf(var + 1e-5f);
    float4 wv = *(const float4*)(gw + lane*4);
    float4 bv = *(const float4*)(gb + lane*4);
    st_half4(g_hw + (size_t)warp*128 + lane*4,
             (v.x - mean)*rstd*wv.x + bv.x,
             (v.y - mean)*rstd*wv.y + bv.y,
             (v.z - mean)*rstd*wv.z + bv.z,
             (v.w - mean)*rstd*wv.w + bv.w);
}

// ---------------- patch-merge gather + LN(512): g_xres -> g_o (fp16) ------
__global__ void merge_ln_kernel(const float* __restrict__ gw, const float* __restrict__ gb)
{
    int warp = (blockIdx.x * blockDim.x + threadIdx.x) >> 5;
    int lane = threadIdx.x & 31;
    int b   = warp / 784;
    int rem = warp - b * 784;
    int i2 = rem / 28;
    int j2 = rem - i2 * 28;
    int i0 = 2*i2, j0 = 2*j2;
    const float* p0 = g_xres + (((size_t)b*56 + i0    )*56 + j0    )*128;
    const float* p1 = g_xres + (((size_t)b*56 + i0 + 1)*56 + j0    )*128;
    const float* p2 = g_xres + (((size_t)b*56 + i0    )*56 + j0 + 1)*128;
    const float* p3 = g_xres + (((size_t)b*56 + i0 + 1)*56 + j0 + 1)*128;
    float4 v[4];
    v[0] = *(const float4*)(p0 + lane*4);
    v[1] = *(const float4*)(p1 + lane*4);
    v[2] = *(const float4*)(p2 + lane*4);
    v[3] = *(const float4*)(p3 + lane*4);
    float s = 0.f, ss = 0.f;
    #pragma unroll
    for (int q = 0; q < 4; q++) {
        s  += v[q].x + v[q].y + v[q].z + v[q].w;
        ss += v[q].x*v[q].x + v[q].y*v[q].y + v[q].z*v[q].z + v[q].w*v[q].w;
    }
    #pragma unroll
    for (int o = 16; o; o >>= 1) {
        s  += __shfl_xor_sync(0xffffffffu, s,  o);
        ss += __shfl_xor_sync(0xffffffffu, ss, o);
    }
    float mean = s * (1.0f/512.0f);
    float var  = ss * (1.0f/512.0f) - mean*mean;
    float rstd = rsqrtf(var + 1e-5f);
    __half* out = g_o + (size_t)warp*512;
    #pragma unroll
    for (int q = 0; q < 4; q++) {
        int c = q*128 + lane*4;
        float4 wv = *(const float4*)(gw + c);
        float4 bv = *(const float4*)(gb + c);
        st_half4(out + c,
                 (v[q].x - mean)*rstd*wv.x + bv.x,
                 (v[q].y - mean)*rstd*wv.y + bv.y,
                 (v[q].z - mean)*rstd*wv.z + bv.z,
                 (v[q].w - mean)*rstd*wv.w + bv.w);
    }
}

// ---------------- MMA attention: block = one window, warp = one head ------
// fp16 I/O, tf32 internals (unchanged, proven correct).
#define AQ_STR 132
#define AK_STR 132
#define AV_STR 136
#define AP_STR 60
#define AOFF_K (64*AQ_STR)                  // 8448
#define AOFF_V (AOFF_K + 56*AK_STR)         // 15840
#define AOFF_P (AOFF_V + 56*AV_STR)         // 23456
#define AOFF_I (AOFF_P + 4*16*AP_STR)       // 27296
#define ATT_SMEM ((AOFF_I + 4*16)*4)        // 109440 bytes

__global__ __launch_bounds__(128) void attn_kernel(
    const __half* __restrict__ qkv, __half* __restrict__ outp)
{
    extern __shared__ float sm[];
    float* qs = sm;
    float* ks = sm + AOFF_K;
    float* vs = sm + AOFF_V;
    const int t    = threadIdx.x;
    const int warp = t >> 5;
    const int lane = t & 31;
    const int win  = blockIdx.x;
    float* Pt   = sm + AOFF_P + warp*16*AP_STR;
    float* invs = sm + AOFF_I + warp*16;

    const __half* base = qkv + (size_t)win*49*384;
    for (int idx = t; idx < 49*48; idx += 128) {
        int row = idx / 48;
        int sub = idx - row*48;
        int kind = sub >> 4;
        int c8 = sub & 15;
        uint4 hv = *(const uint4*)(base + (size_t)row*384 + kind*128 + c8*8);
        const __half2* hp = (const __half2*)&hv;
        float* dst = (kind == 0 ? qs + row*AQ_STR :
                      kind == 1 ? ks + row*AK_STR : vs + row*AV_STR) + c8*8;
        float2 f0 = __half22float2(hp[0]);
        float2 f1 = __half22float2(hp[1]);
        float2 f2 = __half22float2(hp[2]);
        float2 f3 = __half22float2(hp[3]);
        float4 o0; o0.x = f0.x; o0.y = f0.y; o0.z = f1.x; o0.w = f1.y;
        float4 o1; o1.x = f2.x; o1.y = f2.y; o1.z = f3.x; o1.w = f3.y;
        *(float4*)dst = o0;
        *(float4*)(dst + 4) = o1;
    }
    for (int idx = t; idx < 7*AV_STR; idx += 128) {
        int r = idx / AV_STR, c = idx - r*AV_STR;
        vs[(49+r)*AV_STR + c] = 0.f;
        if (c < AK_STR) ks[(49+r)*AK_STR + c] = 0.f;
    }
    __syncthreads();

    const int h   = warp;
    const int qr  = lane >> 2;
    const int qc  = lane & 3;
    const int h32 = h * 32;
    const float* comb = g_bias + (size_t)((win & 63)*4 + h)*2401;
    __half* obase = outp + (size_t)win*49*128 + h32;

    for (int mt = 0; mt < 4; mt++) {
        const int r0 = mt*16 + qr;
        const int r1 = r0 + 8;
        float s[7][4];
        #pragma unroll
        for (int jn = 0; jn < 7; jn++)
            #pragma unroll
            for (int c = 0; c < 4; c++) s[jn][c] = 0.f;
        #pragma unroll
        for (int kb = 0; kb < 32; kb += 8) {
            uint32_t a[4];
            a[0] = __float_as_uint(qs[(size_t)r0*AQ_STR + h32 + kb + qc    ]);
            a[1] = __float_as_uint(qs[(size_t)r1*AQ_STR + h32 + kb + qc    ]);
            a[2] = __float_as_uint(qs[(size_t)r0*AQ_STR + h32 + kb + qc + 4]);
            a[3] = __float_as_uint(qs[(size_t)r1*AQ_STR + h32 + kb + qc + 4]);
            #pragma unroll
            for (int jn = 0; jn < 7; jn++) {
                int n0 = jn*8 + qr;
                uint32_t b0 = __float_as_uint(ks[(size_t)n0*AK_STR + h32 + kb + qc    ]);
                uint32_t b1 = __float_as_uint(ks[(size_t)n0*AK_STR + h32 + kb + qc + 4]);
                mma_tf32(s[jn], a, b0, b1);
            }
        }
        const bool v0 = (r0 < 49), v1 = (r1 < 49);
        float mx0 = -1e30f, mx1 = -1e30f;
        #pragma unroll
        for (int jn = 0; jn < 7; jn++) {
            #pragma unroll
            for (int e = 0; e < 2; e++) {
                int col = jn*8 + qc*2 + e;
                if (col < 49) {
                    if (v0) s[jn][e]     += comb[r0*49 + col];
                    if (v1) s[jn][2 + e] += comb[r1*49 + col];
                } else {
                    s[jn][e] = -1e30f; s[jn][2 + e] = -1e30f;
                }
                mx0 = fmaxf(mx0, s[jn][e]);
                mx1 = fmaxf(mx1, s[jn][2 + e]);
            }
        }
        #pragma unroll
        for (int o = 1; o <= 2; o <<= 1) {
            mx0 = fmaxf(mx0, __shfl_xor_sync(0xffffffffu, mx0, o));
            mx1 = fmaxf(mx1, __shfl_xor_sync(0xffffffffu, mx1, o));
        }
        float sum0 = 0.f, sum1 = 0.f;
        #pragma unroll
        for (int jn = 0; jn < 7; jn++) {
            #pragma unroll
            for (int e = 0; e < 2; e++) {
                int col = jn*8 + qc*2 + e;
                float e0 = __expf(s[jn][e]     - mx0);
                float e1 = __expf(s[jn][2 + e] - mx1);
                sum0 += e0; sum1 += e1;
                Pt[qr*AP_STR       + col] = tf32r(e0);
                Pt[(qr + 8)*AP_STR + col] = tf32r(e1);
            }
        }
        #pragma unroll
        for (int o = 1; o <= 2; o <<= 1) {
            sum0 += __shfl_xor_sync(0xffffffffu, sum0, o);
            sum1 += __shfl_xor_sync(0xffffffffu, sum1, o);
        }
        if (qc == 0) {
            invs[qr]     = 1.0f / sum0;
            invs[qr + 8] = 1.0f / sum1;
        }
        __syncwarp();
        float o[4][4];
        #pragma unroll
        for (int jn = 0; jn < 4; jn++)
            #pragma unroll
            for (int c = 0; c < 4; c++) o[jn][c] = 0.f;
        #pragma unroll
        for (int ks2 = 0; ks2 < 7; ks2++) {
            const int kb = ks2*8;
            uint32_t a[4];
            a[0] = __float_as_uint(Pt[qr*AP_STR       + kb + qc    ]);
            a[1] = __float_as_uint(Pt[(qr + 8)*AP_STR + kb + qc    ]);
            a[2] = __float_as_uint(Pt[qr*AP_STR       + kb + qc + 4]);
            a[3] = __float_as_uint(Pt[(qr + 8)*AP_STR + kb + qc + 4]);
            #pragma unroll
            for (int jn = 0; jn < 4; jn++) {
                int n0 = jn*8 + qr;
                uint32_t b0 = __float_as_uint(vs[(size_t)(kb + qc    )*AV_STR + h32 + n0]);
                uint32_t b1 = __float_as_uint(vs[(size_t)(kb + qc + 4)*AV_STR + h32 + n0]);
                mma_tf32(o[jn], a, b0, b1);
            }
        }
        float i0 = invs[qr], i1 = invs[qr + 8];
        #pragma unroll
        for (int jn = 0; jn < 4; jn++) {
            int col = jn*8 + qc*2;
            if (v0) {
                __half2 f = __floats2half2_rn(o[jn][0]*i0, o[jn][1]*i0);
                *(__half2*)(obase + (size_t)r0*128 + col) = f;
            }
            if (v1) {
                __half2 f = __floats2half2_rn(o[jn][2]*i1, o[jn][3]*i1);
                *(__half2*)(obase + (size_t)r1*128 + col) = f;
            }
        }
        __syncwarp();
    }
}

// ---------------- FP16 tensor-core GEMM, 3-stage ring, 3 CTAs/SM ----------
// C[M,Nd] = A[M,K] @ W[Nd,K]^T + epilogue. A and W are fp16.
// Block tile 128x64, BK=32, 8 warps (4m x 2n), warp tile 32x32, m16n8k16.
// launch_bounds(256,3): ~70 regs -> 24 warps/SM (vs 16 at 128x128 tile),
// attacking the dependency-stall regime the profile shows (no pipe >52%).
// Loop: wait -> sync -> prefetch(slot+2) -> mma(slot); 1 barrier per iter.
// Fragments via ldmatrix.m8n8.x4.b16 (8 LDSM / 16 MMA per BK-iter).
#define TG_STG_BYTES (192*80)       // one stage: (128 A + 64 B rows) * 80B
#define TG_NSTG 3
#define TG_SMEM (TG_STG_BYTES*TG_NSTG)   // 46080 bytes

template<int EPI>
__global__ __launch_bounds__(256, 3) void tgemm_kernel(
    const __half* __restrict__ A, const __half* __restrict__ W,
    const float* __restrict__ bias, void* __restrict__ Cv,
    const float* __restrict__ aux, int M, int Nd, int K)
{
    extern __shared__ __align__(16) char dsm[];
    const int t    = threadIdx.x;
    const int warp = t >> 5;
    const int lane = t & 31;
    const int qr   = lane >> 2;
    const int qc   = lane & 3;
    const int wm   = warp & 3;    // m warp 0..3
    const int wn   = warp >> 2;   // n warp 0..1
    const int bm   = blockIdx.y * 128;
    const int bn   = blockIdx.x * 64;
    const int rowX = t >> 2;      // 0..63
    const int cX   = t & 3;       // 8-half chunk within 32-half row slice

    const __half* aG = A + (size_t)(bm + rowX)*K + cX*8;
    const __half* wG = W + (size_t)(bn + rowX)*K + cX*8;
    const size_t r64 = (size_t)64 * K;

    uint32_t s0 = (uint32_t)__cvta_generic_to_shared(dsm);
    const uint32_t sA = s0 + rowX*80 + cX*16;
    const uint32_t sB = sA + 128*80;

    // ldmatrix per-lane address offset: row (lane&15), half-col (lane>>4)*8
    const uint32_t laneOff = (uint32_t)(lane & 15)*80 + (uint32_t)(lane >> 4)*16;

    float acc[2][4][4] = {};
    const int iters = K >> 5;   // >= 4 always (K = 128 or 512)

    #define TG_STAGE_LOAD(st, kk) do {                        \
        uint32_t off_ = (uint32_t)(st)*TG_STG_BYTES;          \
        const __half* ag_ = aG + (size_t)(kk)*32;             \
        const __half* wg_ = wG + (size_t)(kk)*32;             \
        cp_async16(sA + off_,         ag_);                   \
        cp_async16(sA + off_ + 64*80, ag_ + r64);             \
        cp_async16(sB + off_,         wg_);                   \
        cp_commit();                                          \
    } while (0)

    // prologue: stages 0 and 1
    TG_STAGE_LOAD(0, 0);
    TG_STAGE_LOAD(1, 1);

    int slot = 0;
    for (int it = 0; it < iters; it++) {
        if (it + 1 < iters) cp_wait1(); else cp_wait0();
        __syncthreads();
        if (it + 2 < iters) {
            int ps = slot + 2; if (ps >= TG_NSTG) ps -= TG_NSTG;
            TG_STAGE_LOAD(ps, it + 2);
        }

        const uint32_t stg   = s0 + (uint32_t)slot*TG_STG_BYTES;
        const uint32_t aBase = stg + (uint32_t)(wm*32)*80;
        const uint32_t bBase = stg + 128*80 + (uint32_t)(wn*32)*80;
        #pragma unroll
        for (int ks = 0; ks < 2; ks++) {
            const uint32_t kof = (uint32_t)ks*32;   // 16 halves = 32 bytes
            uint32_t af[2][4];
            ldsm_x4(af[0], aBase + kof + laneOff);
            ldsm_x4(af[1], aBase + 16*80 + kof + laneOff);
            #pragma unroll
            for (int p = 0; p < 2; p++) {
                uint32_t bf[4];   // {b0(j=2p), b0(j=2p+1), b1(2p), b1(2p+1)}
                ldsm_x4(bf, bBase + (uint32_t)(p*16)*80 + kof + laneOff);
                mma_f16(acc[0][2*p    ], af[0], bf[0], bf[2]);
                mma_f16(acc[1][2*p    ], af[1], bf[0], bf[2]);
                mma_f16(acc[0][2*p + 1], af[0], bf[1], bf[3]);
                mma_f16(acc[1][2*p + 1], af[1], bf[1], bf[3]);
            }
        }
        if (++slot == TG_NSTG) slot = 0;
    }
    #undef TG_STAGE_LOAD

    // ---- epilogue (vectorized pair stores) ----
    float*  Cf = (float*)Cv;
    __half* Ch = (__half*)Cv;
    #pragma unroll
    for (int i = 0; i < 2; i++) {
        #pragma unroll
        for (int half_ = 0; half_ < 2; half_++) {
            const int m = bm + wm*32 + i*16 + qr + half_*8;
            size_t obase;
            if (EPI == 2) {
                int win = m / 49, nn = m - win*49;
                int bb = win >> 6, w = win & 63;
                int n7 = nn / 7;
                int pi = (w >> 3)*7 + n7;
                int pj = (w & 7)*7 + (nn - n7*7);
                int ii = pi + 3; if (ii >= 56) ii -= 56;
                int jj = pj + 3; if (jj >= 56) jj -= 56;
                obase = (((size_t)bb*56 + ii)*56 + jj)*128;
            } else {
                obase = (size_t)m * Nd;
            }
            #pragma unroll
            for (int j = 0; j < 4; j++) {
                const int n = bn + wn*32 + j*8 + qc*2;
                float v0 = acc[i][j][half_*2];
                float v1 = acc[i][j][half_*2 + 1];
                if (EPI == 0) {
                    float2 f; f.x = v0; f.y = v1;
                    *(float2*)(Cf + obase + n) = f;
                } else if (EPI == 1) {
                    v0 += bias[n]; v1 += bias[n + 1];
                    if (n < 128) { v0 *= 0.17677669529663687f; v1 *= 0.17677669529663687f; }
                    *(__half2*)(Ch + obase + n) = __floats2half2_rn(v0, v1);
                } else if (EPI == 2) {
                    v0 += bias[n]; v1 += bias[n + 1];
                    float2 a2 = *(const float2*)(aux + obase + n);
                    float2 f; f.x = v0 + a2.x; f.y = v1 + a2.y;
                    *(float2*)(Cf + obase + n) = f;
                } else if (EPI == 3) {
                    v0 += bias[n]; v1 += bias[n + 1];
                    v0 = 0.5f * v0 * (1.0f + erff(v0 * 0.70710678118654752f));
                    v1 = 0.5f * v1 * (1.0f + erff(v1 * 0.70710678118654752f));
                    *(__half2*)(Ch + obase + n) = __floats2half2_rn(v0, v1);
                } else { // EPI == 4
                    v0 += bias[n]; v1 += bias[n + 1];
                    float2 a2 = *(const float2*)(aux + obase + n);
                    float2 f; f.x = v0 + a2.x; f.y = v1 + a2.y;
                    *(float2*)(Cf + obase + n) = f;
                }
            }
        }
    }
}

// ---------------- launcher ----------------
extern "C" void kernel_launch(void* const* d_in, const int* in_sizes, int n_in,
                              void* d_out, int out_size)
{
    const float* x       = (const float*)d_in[0];
    const float* n1w     = (const float*)d_in[1];
    const float* n1b     = (const float*)d_in[2];
    const float* qkv_w   = (const float*)d_in[3];
    const float* qkv_b   = (const float*)d_in[4];
    const float* proj_w  = (const float*)d_in[5];
    const float* proj_b  = (const float*)d_in[6];
    const float* rpb     = (const float*)d_in[7];
    const float* n2w     = (const float*)d_in[8];
    const float* n2b     = (const float*)d_in[9];
    const float* fc1_w   = (const float*)d_in[10];
    const float* fc1_b   = (const float*)d_in[11];
    const float* fc2_w   = (const float*)d_in[12];
    const float* fc2_b   = (const float*)d_in[13];
    const float* mnw     = (const float*)d_in[14];
    const float* mnb     = (const float*)d_in[15];
    const float* merge_w = (const float*)d_in[16];
    const int*   rel_idx = (const int*)d_in[17];
    const float* amask   = (const float*)d_in[18];
    float* out = (float*)d_out;

    __half *hw, *qkv, *o, *fc1, *wt;
    float *xres;
    cudaGetSymbolAddress((void**)&hw,   g_hw);
    cudaGetSymbolAddress((void**)&qkv,  g_qkv);
    cudaGetSymbolAddress((void**)&o,    g_o);
    cudaGetSymbolAddress((void**)&xres, g_xres);
    cudaGetSymbolAddress((void**)&fc1,  g_fc1);
    cudaGetSymbolAddress((void**)&wt,   g_wt);

    cudaFuncSetAttribute(tgemm_kernel<0>, cudaFuncAttributeMaxDynamicSharedMemorySize, TG_SMEM);
    cudaFuncSetAttribute(tgemm_kernel<1>, cudaFuncAttributeMaxDynamicSharedMemorySize, TG_SMEM);
    cudaFuncSetAttribute(tgemm_kernel<2>, cudaFuncAttributeMaxDynamicSharedMemorySize, TG_SMEM);
    cudaFuncSetAttribute(tgemm_kernel<3>, cudaFuncAttributeMaxDynamicSharedMemorySize, TG_SMEM);
    cudaFuncSetAttribute(tgemm_kernel<4>, cudaFuncAttributeMaxDynamicSharedMemorySize, TG_SMEM);
    cudaFuncSetAttribute(attn_kernel, cudaFuncAttributeMaxDynamicSharedMemorySize, ATT_SMEM);

    // 0. pre-convert weights to fp16; build combined attention bias table
    round_w_kernel<<<WTOT/256, 256>>>(qkv_w, proj_w, fc1_w, fc2_w, merge_w);
    bias_prep_kernel<<<dim3(64, 4), 256>>>(rpb, rel_idx, amask);
    // 1. LN1 + roll + window partition (fp16 out)
    ln1_win_kernel<<<PIX/8, 256>>>(x, n1w, n1b);
    // 2. qkv GEMM (scale folded into q; fp16 out)
    tgemm_kernel<1><<<dim3(6, M1_/128), 256, TG_SMEM>>>(hw, wt + WOFF_QKV, qkv_b, qkv, nullptr, M1_, 384, 128);
    // 3. windowed attention (tensor cores; fp16 out)
    attn_kernel<<<4096, 128, ATT_SMEM>>>(qkv, o);
    // 4. proj GEMM + window-reverse + roll-back + residual -> xres (fp32, pixel layout)
    tgemm_kernel<2><<<dim3(2, M1_/128), 256, TG_SMEM>>>(o, wt + WOFF_PROJ, proj_b, xres, x, M1_, 128, 128);
    // 5. LN2: xres -> g_hw (fp16)
    ln2_kernel<<<PIX/8, 256>>>(n2w, n2b);
    // 6. fc1 GEMM + GELU (fp16 out)
    tgemm_kernel<3><<<dim3(8, M1_/128), 256, TG_SMEM>>>(hw, wt + WOFF_FC1, fc1_b, fc1, nullptr, M1_, 512, 128);
    // 7. fc2 GEMM + residual (fp32, in place on xres)
    tgemm_kernel<4><<<dim3(2, M1_/128), 256, TG_SMEM>>>(fc1, wt + WOFF_FC2, fc2_b, xres, xres, M1_, 128, 512);
    // 8. patch-merge gather + LN(512): xres -> g_o (fp16, reuse as xm)
    merge_ln_kernel<<<M2_/8, 256>>>(mnw, mnb);
    // 9. merge GEMM -> output (fp32)
    tgemm_kernel<0><<<dim3(4, M2_/128), 256, TG_SMEM>>>(o, wt + WOFF_MRG, nullptr, out, nullptr, M2_, 256, 512);
}